// round 12
// baseline (speedup 1.0000x reference)
#include <cuda_runtime.h>
#include <cuda_bf16.h>
#include <math.h>
#include <stdint.h>

// Problem constants
#define BB     4
#define SEQ    2048
#define DMODEL 1024
#define NH     16
#define DEPTH  64
#define MROWS  (BB*SEQ)   // 8192

// ---------------------------------------------------------------------------
// Scratch (static __device__ arrays — allocation-free per harness rules)
// ---------------------------------------------------------------------------
__device__ unsigned short g_qh[BB*NH*SEQ*DEPTH], g_ql[BB*NH*SEQ*DEPTH];
__device__ unsigned short g_kh[BB*NH*SEQ*DEPTH], g_kl[BB*NH*SEQ*DEPTH];
__device__ unsigned short g_vh[BB*NH*SEQ*DEPTH], g_vl[BB*NH*SEQ*DEPTH];
__device__ unsigned short g_ah[MROWS*DMODEL],    g_al[MROWS*DMODEL];
__device__ unsigned short g_xh[MROWS*DMODEL],    g_xl[MROWS*DMODEL];
__device__ unsigned short g_yh[MROWS*DMODEL],    g_yl[MROWS*DMODEL];
__device__ unsigned short g_wqh[DMODEL*DMODEL],  g_wql[DMODEL*DMODEL];
__device__ unsigned short g_wkh[DMODEL*DMODEL],  g_wkl[DMODEL*DMODEL];
__device__ unsigned short g_wvh[DMODEL*DMODEL],  g_wvl[DMODEL*DMODEL];
__device__ unsigned short g_woh[DMODEL*DMODEL],  g_wol[DMODEL*DMODEL];

// ---------------------------------------------------------------------------
// Baseline-PTX helpers (no tcgen05 — harness compiles for compute_103!)
// ---------------------------------------------------------------------------
__device__ __forceinline__ uint32_t smem_u32(const void* p) {
    uint32_t r;
    asm("{ .reg .u64 t; cvta.to.shared.u64 t, %1; cvt.u32.u64 %0, t; }"
        : "=r"(r) : "l"(p));
    return r;
}
__device__ __forceinline__ void cp_async16(uint32_t saddr, const void* gaddr) {
    asm volatile("cp.async.cg.shared.global [%0], [%1], 16;"
                 :: "r"(saddr), "l"(gaddr) : "memory");
}
__device__ __forceinline__ void cp_commit() {
    asm volatile("cp.async.commit_group;" ::: "memory");
}
template <int N>
__device__ __forceinline__ void cp_wait() {
    asm volatile("cp.async.wait_group %0;" :: "n"(N) : "memory");
}
__device__ __forceinline__ void ldmx4(uint32_t* r, uint32_t a) {
    asm volatile("ldmatrix.sync.aligned.m8n8.x4.shared.b16 {%0,%1,%2,%3}, [%4];"
                 : "=r"(r[0]), "=r"(r[1]), "=r"(r[2]), "=r"(r[3]) : "r"(a));
}
__device__ __forceinline__ void ldmx2(uint32_t* r, uint32_t a) {
    asm volatile("ldmatrix.sync.aligned.m8n8.x2.shared.b16 {%0,%1}, [%2];"
                 : "=r"(r[0]), "=r"(r[1]) : "r"(a));
}
__device__ __forceinline__ void ldmx4t(uint32_t* r, uint32_t a) {
    asm volatile("ldmatrix.sync.aligned.m8n8.x4.trans.shared.b16 {%0,%1,%2,%3}, [%4];"
                 : "=r"(r[0]), "=r"(r[1]), "=r"(r[2]), "=r"(r[3]) : "r"(a));
}
__device__ __forceinline__ void mma16816(float* d, const uint32_t* a, const uint32_t* b) {
    asm volatile(
        "mma.sync.aligned.m16n8k16.row.col.f32.bf16.bf16.f32 "
        "{%0,%1,%2,%3}, {%4,%5,%6,%7}, {%8,%9}, {%0,%1,%2,%3};"
        : "+f"(d[0]), "+f"(d[1]), "+f"(d[2]), "+f"(d[3])
        : "r"(a[0]), "r"(a[1]), "r"(a[2]), "r"(a[3]), "r"(b[0]), "r"(b[1]));
}

// Split a float pair into bf16 hi/lo packed b32s (low half = first value)
__device__ __forceinline__ void pack_hilo(float f0, float f1, uint32_t& h, uint32_t& l) {
    __nv_bfloat162 hb = __floats2bfloat162_rn(f0, f1);
    uint32_t hu = *reinterpret_cast<uint32_t*>(&hb);
    float r0 = f0 - __int_as_float(hu << 16);
    float r1 = f1 - __int_as_float(hu & 0xFFFF0000u);
    __nv_bfloat162 lb = __floats2bfloat162_rn(r0, r1);
    h = hu;
    l = *reinterpret_cast<uint32_t*>(&lb);
}

// FMA-pipe 2^t (t <= 0 in all our uses). deg-5 Taylor on [-0.5,0.5], err ~2.4e-6.
__device__ __forceinline__ float exp2p(float t) {
    t = fmaxf(t, -126.f);
    float z = t + 12582912.f;          // 1.5*2^23 round-to-int trick
    float n = z - 12582912.f;
    float f = t - n;
    float p = 0.0013333558f;
    p = fmaf(p, f, 0.0096181291f);
    p = fmaf(p, f, 0.0555041087f);
    p = fmaf(p, f, 0.2402265070f);
    p = fmaf(p, f, 0.6931471806f);
    p = fmaf(p, f, 1.0f);
    int e = (__float_as_int(z) + (127 - 0x4B400000)) << 23;
    return __int_as_float(e) * p;
}

#define L2E 1.4426950408889634f

// ---------------------------------------------------------------------------
// Batched fp32 -> bf16 hi/lo conversions (2-way and 4-way over blockIdx.y)
// ---------------------------------------------------------------------------
__device__ __forceinline__ void cvt_one(const float4* src, __nv_bfloat162* hi,
                                        __nv_bfloat162* lo, int i) {
    float4 v = src[i];
    uint32_t h0, l0, h1, l1;
    pack_hilo(v.x, v.y, h0, l0);
    pack_hilo(v.z, v.w, h1, l1);
    hi[2*i + 0] = *reinterpret_cast<__nv_bfloat162*>(&h0);
    hi[2*i + 1] = *reinterpret_cast<__nv_bfloat162*>(&h1);
    lo[2*i + 0] = *reinterpret_cast<__nv_bfloat162*>(&l0);
    lo[2*i + 1] = *reinterpret_cast<__nv_bfloat162*>(&l1);
}

__global__ __launch_bounds__(256) void cvt_hilo2(
    const float4* __restrict__ s0, __nv_bfloat162* __restrict__ h0, __nv_bfloat162* __restrict__ l0,
    const float4* __restrict__ s1, __nv_bfloat162* __restrict__ h1, __nv_bfloat162* __restrict__ l1,
    int n4)
{
    int i = blockIdx.x * blockDim.x + threadIdx.x;
    if (i >= n4) return;
    if (blockIdx.y == 0) cvt_one(s0, h0, l0, i);
    else                 cvt_one(s1, h1, l1, i);
}

__global__ __launch_bounds__(256) void cvt_hilo4(
    const float4* __restrict__ s0, __nv_bfloat162* __restrict__ h0, __nv_bfloat162* __restrict__ l0,
    const float4* __restrict__ s1, __nv_bfloat162* __restrict__ h1, __nv_bfloat162* __restrict__ l1,
    const float4* __restrict__ s2, __nv_bfloat162* __restrict__ h2, __nv_bfloat162* __restrict__ l2,
    const float4* __restrict__ s3, __nv_bfloat162* __restrict__ h3, __nv_bfloat162* __restrict__ l3,
    int n4)
{
    int i = blockIdx.x * blockDim.x + threadIdx.x;
    if (i >= n4) return;
    switch (blockIdx.y) {
        case 0: cvt_one(s0, h0, l0, i); break;
        case 1: cvt_one(s1, h1, l1, i); break;
        case 2: cvt_one(s2, h2, l2, i); break;
        default: cvt_one(s3, h3, l3, i); break;
    }
}

// ---------------------------------------------------------------------------
// mma.sync bf16x3 GEMM (validated in R6/R7) — unchanged.
// ---------------------------------------------------------------------------
#define GK       1024
#define BKE      32
#define NSTG     (GK / BKE)          // 32
#define TPAD     40
#define TILE_B   (128 * TPAD * 2)    // 10240
#define STAGE_B  (4 * TILE_B)
#define GSMEM    (2 * STAGE_B)       // 81920

__device__ __forceinline__ void issue_stage(uint32_t sbase, int s, int k0, int m0, int n0,
                                            int tid,
                                            const __nv_bfloat16* Ah, const __nv_bfloat16* Al,
                                            const __nv_bfloat16* Bh, const __nv_bfloat16* Bl)
{
    const __nv_bfloat16* gsrc[4] = {Ah, Al, Bh, Bl};
    #pragma unroll
    for (int t = 0; t < 4; t++) {
        const int r0 = (t < 2) ? m0 : n0;
        const char* g = (const char*)(gsrc[t] + (size_t)r0 * GK + k0);
        uint32_t sb = sbase + s * STAGE_B + t * TILE_B;
        #pragma unroll
        for (int i = 0; i < 2; i++) {
            int slot = tid + i * 256;
            int row  = slot >> 2;
            int c16  = (slot & 3) * 16;
            cp_async16(sb + row * (TPAD * 2) + c16,
                       g + (size_t)row * (GK * 2) + c16);
        }
    }
}

template <int LAYOUT>
__global__ __launch_bounds__(256) void gemm_bf16x3(
    const __nv_bfloat16* __restrict__ Ah, const __nv_bfloat16* __restrict__ Al,
    const __nv_bfloat16* __restrict__ Bh, const __nv_bfloat16* __restrict__ Bl,
    float* __restrict__ C,
    unsigned short* __restrict__ Ch, unsigned short* __restrict__ Cl,
    float scale)
{
    extern __shared__ __align__(128) char smem[];
    const int tid = threadIdx.x;
    const int wid = tid >> 5;
    const int lane = tid & 31;
    const int warp_m = wid >> 2;
    const int warp_n = wid & 3;
    const int m0 = blockIdx.y * 128;
    const int n0 = blockIdx.x * 128;

    const uint32_t sbase = smem_u32(smem);

    float d[4][4][4];
    #pragma unroll
    for (int mf = 0; mf < 4; mf++)
        #pragma unroll
        for (int nf = 0; nf < 4; nf++)
            #pragma unroll
            for (int r = 0; r < 4; r++) d[mf][nf][r] = 0.f;

    const int arow = warp_m * 64 + (lane & 15);
    const int acol8 = (lane >> 4) * 8;
    const int brow = warp_n * 32 + (lane & 7);
    const int bcol8 = ((lane >> 3) & 1) * 8;

    issue_stage(sbase, 0, 0, m0, n0, tid, Ah, Al, Bh, Bl);
    cp_commit();

    for (int it = 0; it < NSTG; it++) {
        const int s = it & 1;
        if (it + 1 < NSTG) {
            issue_stage(sbase, s ^ 1, (it + 1) * BKE, m0, n0, tid, Ah, Al, Bh, Bl);
            cp_commit();
            cp_wait<1>();
        } else {
            cp_wait<0>();
        }
        __syncthreads();

        const uint32_t As_h = sbase + s * STAGE_B;
        const uint32_t As_l = As_h + TILE_B;
        const uint32_t Bs_h = As_h + 2 * TILE_B;
        const uint32_t Bs_l = As_h + 3 * TILE_B;

        #pragma unroll
        for (int ks = 0; ks < 2; ks++) {
            const int kb = ks * 16;
            uint32_t ah[4][4], al[4][4], bh[4][2], bl[4][2];
            #pragma unroll
            for (int mf = 0; mf < 4; mf++) {
                uint32_t off = (uint32_t)((arow + mf * 16) * TPAD + kb + acol8) * 2;
                ldmx4(ah[mf], As_h + off);
                ldmx4(al[mf], As_l + off);
            }
            #pragma unroll
            for (int nf = 0; nf < 4; nf++) {
                uint32_t off = (uint32_t)((brow + nf * 8) * TPAD + kb + bcol8) * 2;
                ldmx2(bh[nf], Bs_h + off);
                ldmx2(bl[nf], Bs_l + off);
            }
            #pragma unroll
            for (int mf = 0; mf < 4; mf++)
                #pragma unroll
                for (int nf = 0; nf < 4; nf++) {
                    mma16816(d[mf][nf], ah[mf], bh[nf]);
                    mma16816(d[mf][nf], ah[mf], bl[nf]);
                    mma16816(d[mf][nf], al[mf], bh[nf]);
                }
        }
        __syncthreads();
    }

    const int g = lane >> 2;
    const int tg = lane & 3;
    #pragma unroll
    for (int mf = 0; mf < 4; mf++) {
        #pragma unroll
        for (int nf = 0; nf < 4; nf++) {
            int m = m0 + warp_m * 64 + mf * 16 + g;
            int n = n0 + warp_n * 32 + nf * 8 + tg * 2;
            #pragma unroll
            for (int half = 0; half < 2; half++) {
                float vx = d[mf][nf][half * 2 + 0] * scale;
                float vy = d[mf][nf][half * 2 + 1] * scale;
                int mm = m + half * 8;
                if (LAYOUT == 0) {
                    float2 v; v.x = vx; v.y = vy;
                    *(float2*)&C[(size_t)mm * DMODEL + n] = v;
                } else {
                    uint32_t hp, lp;
                    pack_hilo(vx, vy, hp, lp);
                    int bI = mm >> 11;
                    int sI = mm & (SEQ - 1);
                    int hI = n >> 6;
                    int dd = n & (DEPTH - 1);
                    size_t idx = (((size_t)(bI * NH + hI)) * SEQ + sI) * DEPTH + dd;
                    *(uint32_t*)&Ch[idx] = hp;
                    *(uint32_t*)&Cl[idx] = lp;
                }
            }
        }
    }
}

// ---------------------------------------------------------------------------
// Flash attention v3: Q fragments hoisted to registers; bias pre-loaded into
// the S accumulator (MMA accumulates on top — latency hidden by MMA issue).
// ---------------------------------------------------------------------------
#define FPITCH 72
#define FROWB  (FPITCH*2)              // 144
#define FQH    0
#define FQL    (128*FROWB)             // 18432
#define FKV0   (2*128*FROWB)           // 36864
#define FSTG   (4*64*FROWB)            // 36864
#define FKH    0
#define FKL    (64*FROWB)
#define FVH    (2*64*FROWB)
#define FVL    (3*64*FROWB)
#define FSMEM  (FKV0 + 2*FSTG)         // 110592

__device__ __forceinline__ void flash_issue_kv(uint32_t sb, int kv0, int tid,
                                               const unsigned short* kh, const unsigned short* kl,
                                               const unsigned short* vh, const unsigned short* vl)
{
    const unsigned short* srcs[4] = {kh, kl, vh, vl};
    #pragma unroll
    for (int i = 0; i < 8; i++) {
        const int t = i >> 1;
        int slot = (i & 1) * 256 + tid;
        int r = slot >> 3;
        int c = slot & 7;
        cp_async16(sb + t * 9216 + r * 144 + c * 16,
                   (const char*)(srcs[t] + (size_t)(kv0 + r) * DEPTH) + c * 16);
    }
}

__global__ __launch_bounds__(256, 1) void flash_v3(const float* __restrict__ bias)
{
    extern __shared__ __align__(128) char smem[];
    const uint32_t sbase = smem_u32(smem);

    const int bh = blockIdx.x;
    const int q0 = blockIdx.y * 128;
    const int b  = bh >> 4;
    const int h  = bh & 15;

    const size_t hb = (size_t)bh * SEQ * DEPTH;
    const unsigned short* qhp = g_qh + hb;
    const unsigned short* qlp = g_ql + hb;
    const unsigned short* khp = g_kh + hb;
    const unsigned short* klp = g_kl + hb;
    const unsigned short* vhp = g_vh + hb;
    const unsigned short* vlp = g_vl + hb;

    const int tid = threadIdx.x;
    const int W = tid >> 5;
    const int lane = tid & 31;
    const int g = lane >> 2;
    const int tg = lane & 3;

    // ---- preload Q (hi+lo) ----
    {
        const unsigned short* src = (tid & 128) ? qlp : qhp;
        uint32_t dst = sbase + ((tid & 128) ? FQL : FQH);
        int row = tid & 127;
        #pragma unroll
        for (int c = 0; c < 8; c++)
            cp_async16(dst + row * 144 + c * 16,
                       (const char*)(src + (size_t)(q0 + row) * DEPTH) + c * 16);
    }
    cp_commit();                                   // group: Q
    flash_issue_kv(sbase + FKV0, 0, tid, khp, klp, vhp, vlp);
    cp_commit();                                   // group: KV0

    const uint32_t aoff = (uint32_t)((W * 16 + (lane & 15)) * FPITCH + ((lane >> 4) & 1) * 8) * 2;
    const uint32_t boff = (uint32_t)((lane & 7) * FPITCH + ((lane >> 3) & 1) * 8) * 2;

    // ---- hoist Q fragments into registers (loop-invariant) ----
    cp_wait<1>();                                  // Q complete (KV0 may be in flight)
    __syncthreads();
    uint32_t ah[4][4], al[4][4];
    #pragma unroll
    for (int ks = 0; ks < 4; ks++) {
        ldmx4(ah[ks], sbase + FQH + aoff + ks * 32);
        ldmx4(al[ks], sbase + FQL + aoff + ks * 32);
    }

    float o[8][4];
    #pragma unroll
    for (int nf = 0; nf < 8; nf++)
        #pragma unroll
        for (int r = 0; r < 4; r++) o[nf][r] = 0.f;
    float mrow[2] = {-INFINITY, -INFINITY};
    float lrow[2] = {0.f, 0.f};

    const float* brow0 = bias + (size_t)(q0 + W * 16 + g) * SEQ + tg * 2;

    for (int it = 0; it < SEQ / 64; it++) {
        const int s = it & 1;
        const int k0 = it * 64;
        if (it + 1 < SEQ / 64) {
            flash_issue_kv(sbase + FKV0 + (s ^ 1) * FSTG, (it + 1) * 64, tid,
                           khp, klp, vhp, vlp);
            cp_commit();
            cp_wait<1>();
        } else {
            cp_wait<0>();
        }
        __syncthreads();

        const uint32_t SB = sbase + FKV0 + s * FSTG;

        // ---- S starts as bias (LDG latency hidden behind MMA issue) ----
        float sacc[8][4];
        {
            const float* bp = brow0 + k0;
            #pragma unroll
            for (int nf = 0; nf < 8; nf++) {
                float2 b0 = *(const float2*)(bp + nf * 8);
                float2 b1 = *(const float2*)(bp + 8 * SEQ + nf * 8);
                sacc[nf][0] = b0.x; sacc[nf][1] = b0.y;
                sacc[nf][2] = b1.x; sacc[nf][3] = b1.y;
            }
        }

        // ---- S += Q K^T (bf16x3) ----
        #pragma unroll
        for (int nf = 0; nf < 8; nf++) {
            const uint32_t bo = SB + (uint32_t)(nf * 8 * FPITCH * 2) + boff;
            #pragma unroll
            for (int ks = 0; ks < 4; ks++) {
                uint32_t kh2[2], kl2[2];
                ldmx2(kh2, bo + FKH + ks * 32);
                ldmx2(kl2, bo + FKL + ks * 32);
                mma16816(sacc[nf], ah[ks], kh2);
                mma16816(sacc[nf], ah[ks], kl2);
                mma16816(sacc[nf], al[ks], kh2);
            }
        }

        // ---- online softmax (rows g and g+8; reduce over 4 tg lanes) ----
        #pragma unroll
        for (int r = 0; r < 2; r++) {
            float mx = fmaxf(sacc[0][2*r], sacc[0][2*r+1]);
            #pragma unroll
            for (int nf = 1; nf < 8; nf++)
                mx = fmaxf(mx, fmaxf(sacc[nf][2*r], sacc[nf][2*r+1]));
            mx = fmaxf(mx, __shfl_xor_sync(0xffffffffu, mx, 1));
            mx = fmaxf(mx, __shfl_xor_sync(0xffffffffu, mx, 2));
            float mnew = fmaxf(mrow[r], mx);
            float mL = mnew * L2E;
            float corr = exp2p(fmaf(mrow[r], L2E, -mL));
            float sum = 0.f;
            #pragma unroll
            for (int nf = 0; nf < 8; nf++) {
                float p0 = exp2p(fmaf(sacc[nf][2*r],   L2E, -mL));
                float p1 = exp2p(fmaf(sacc[nf][2*r+1], L2E, -mL));
                sacc[nf][2*r] = p0; sacc[nf][2*r+1] = p1;
                sum += p0 + p1;
            }
            sum += __shfl_xor_sync(0xffffffffu, sum, 1);
            sum += __shfl_xor_sync(0xffffffffu, sum, 2);
            lrow[r] = lrow[r] * corr + sum;
            mrow[r] = mnew;
            #pragma unroll
            for (int nf = 0; nf < 8; nf++) {
                o[nf][2*r]   *= corr;
                o[nf][2*r+1] *= corr;
            }
        }

        // ---- O += P V (P re-packed in-register to A-fragments, bf16x3) ----
        #pragma unroll
        for (int ks = 0; ks < 4; ks++) {
            uint32_t ph[4], pl[4];
            pack_hilo(sacc[2*ks][0],   sacc[2*ks][1],   ph[0], pl[0]);
            pack_hilo(sacc[2*ks][2],   sacc[2*ks][3],   ph[1], pl[1]);
            pack_hilo(sacc[2*ks+1][0], sacc[2*ks+1][1], ph[2], pl[2]);
            pack_hilo(sacc[2*ks+1][2], sacc[2*ks+1][3], ph[3], pl[3]);
            const uint32_t vro = (uint32_t)((ks * 16 + (lane & 15)) * FPITCH) * 2;
            #pragma unroll
            for (int nfp = 0; nfp < 4; nfp++) {
                uint32_t voff = vro + (uint32_t)((nfp * 2 + ((lane >> 4) & 1)) * 8) * 2;
                uint32_t vh4[4], vl4[4];
                ldmx4t(vh4, SB + FVH + voff);
                ldmx4t(vl4, SB + FVL + voff);
                mma16816(o[nfp*2],     ph, vh4);
                mma16816(o[nfp*2],     ph, vl4);
                mma16816(o[nfp*2],     pl, vh4);
                mma16816(o[nfp*2 + 1], ph, vh4 + 2);
                mma16816(o[nfp*2 + 1], ph, vl4 + 2);
                mma16816(o[nfp*2 + 1], pl, vh4 + 2);
            }
        }
        __syncthreads();
    }

    // ---- epilogue: normalize, emit bf16 hi/lo attn in [B,S,D] layout ----
    const float inv0 = 1.0f / lrow[0];
    const float inv1 = 1.0f / lrow[1];
    const int mr = q0 + W * 16 + g;
    #pragma unroll
    for (int nf = 0; nf < 8; nf++) {
        int col = h * DEPTH + nf * 8 + tg * 2;
        uint32_t hp, lp;
        pack_hilo(o[nf][0] * inv0, o[nf][1] * inv0, hp, lp);
        size_t i0 = ((size_t)b * SEQ + mr) * DMODEL + col;
        *(uint32_t*)&g_ah[i0] = hp;
        *(uint32_t*)&g_al[i0] = lp;
        pack_hilo(o[nf][2] * inv1, o[nf][3] * inv1, hp, lp);
        size_t i1 = ((size_t)b * SEQ + mr + 8) * DMODEL + col;
        *(uint32_t*)&g_ah[i1] = hp;
        *(uint32_t*)&g_al[i1] = lp;
    }
}

// ---------------------------------------------------------------------------
// Launch
// ---------------------------------------------------------------------------
extern "C" void kernel_launch(void* const* d_in, const int* in_sizes, int n_in,
                              void* d_out, int out_size)
{
    const float* x    = (const float*)d_in[0];
    const float* y    = (const float*)d_in[1];
    const float* bias = (const float*)d_in[2];
    const float* Wq   = (const float*)d_in[3];
    const float* Wk   = (const float*)d_in[4];
    const float* Wv   = (const float*)d_in[5];
    const float* Wo   = (const float*)d_in[6];
    float* out = (float*)d_out;

    unsigned short *qh, *ql, *kh, *kl, *vh, *vl, *ah, *al;
    unsigned short *xh, *xl, *yh, *yl;
    unsigned short *wqh, *wql, *wkh, *wkl, *wvh, *wvl, *woh, *wol;
    cudaGetSymbolAddress((void**)&qh, g_qh);   cudaGetSymbolAddress((void**)&ql, g_ql);
    cudaGetSymbolAddress((void**)&kh, g_kh);   cudaGetSymbolAddress((void**)&kl, g_kl);
    cudaGetSymbolAddress((void**)&vh, g_vh);   cudaGetSymbolAddress((void**)&vl, g_vl);
    cudaGetSymbolAddress((void**)&ah, g_ah);   cudaGetSymbolAddress((void**)&al, g_al);
    cudaGetSymbolAddress((void**)&xh, g_xh);   cudaGetSymbolAddress((void**)&xl, g_xl);
    cudaGetSymbolAddress((void**)&yh, g_yh);   cudaGetSymbolAddress((void**)&yl, g_yl);
    cudaGetSymbolAddress((void**)&wqh, g_wqh); cudaGetSymbolAddress((void**)&wql, g_wql);
    cudaGetSymbolAddress((void**)&wkh, g_wkh); cudaGetSymbolAddress((void**)&wkl, g_wkl);
    cudaGetSymbolAddress((void**)&wvh, g_wvh); cudaGetSymbolAddress((void**)&wvl, g_wvl);
    cudaGetSymbolAddress((void**)&woh, g_woh); cudaGetSymbolAddress((void**)&wol, g_wol);

    cudaFuncSetAttribute(gemm_bf16x3<0>, cudaFuncAttributeMaxDynamicSharedMemorySize, GSMEM);
    cudaFuncSetAttribute(gemm_bf16x3<1>, cudaFuncAttributeMaxDynamicSharedMemorySize, GSMEM);
    cudaFuncSetAttribute(flash_v3, cudaFuncAttributeMaxDynamicSharedMemorySize, FSMEM);

    const int n4big = MROWS * DMODEL / 4;
    const int n4w   = DMODEL * DMODEL / 4;

    // batched conversions: x+y in one launch, 4 weights in one launch
    cvt_hilo2<<<dim3(n4big/256, 2), 256>>>(
        (const float4*)x, (__nv_bfloat162*)xh, (__nv_bfloat162*)xl,
        (const float4*)y, (__nv_bfloat162*)yh, (__nv_bfloat162*)yl, n4big);
    cvt_hilo4<<<dim3(n4w/256, 4), 256>>>(
        (const float4*)Wq, (__nv_bfloat162*)wqh, (__nv_bfloat162*)wql,
        (const float4*)Wk, (__nv_bfloat162*)wkh, (__nv_bfloat162*)wkl,
        (const float4*)Wv, (__nv_bfloat162*)wvh, (__nv_bfloat162*)wvl,
        (const float4*)Wo, (__nv_bfloat162*)woh, (__nv_bfloat162*)wol, n4w);

    dim3 ggrid(DMODEL / 128, MROWS / 128);    // (8, 64)
    const float qscale = 0.125f;

    gemm_bf16x3<1><<<ggrid, 256, GSMEM>>>((const __nv_bfloat16*)xh, (const __nv_bfloat16*)xl,
                                          (const __nv_bfloat16*)wqh, (const __nv_bfloat16*)wql,
                                          nullptr, qh, ql, qscale);
    gemm_bf16x3<1><<<ggrid, 256, GSMEM>>>((const __nv_bfloat16*)yh, (const __nv_bfloat16*)yl,
                                          (const __nv_bfloat16*)wkh, (const __nv_bfloat16*)wkl,
                                          nullptr, kh, kl, 1.0f);
    gemm_bf16x3<1><<<ggrid, 256, GSMEM>>>((const __nv_bfloat16*)yh, (const __nv_bfloat16*)yl,
                                          (const __nv_bfloat16*)wvh, (const __nv_bfloat16*)wvl,
                                          nullptr, vh, vl, 1.0f);

    dim3 fgrid(BB * NH, SEQ / 128);           // (64, 16)
    flash_v3<<<fgrid, dim3(256), FSMEM>>>(bias);

    gemm_bf16x3<0><<<ggrid, 256, GSMEM>>>((const __nv_bfloat16*)ah, (const __nv_bfloat16*)al,
                                          (const __nv_bfloat16*)woh, (const __nv_bfloat16*)wol,
                                          out, nullptr, nullptr, 1.0f);
}

// round 15
// speedup vs baseline: 1.0942x; 1.0942x over previous
#include <cuda_runtime.h>
#include <cuda_bf16.h>
#include <math.h>
#include <stdint.h>

// Problem constants
#define BB     4
#define SEQ    2048
#define DMODEL 1024
#define NH     16
#define DEPTH  64
#define MROWS  (BB*SEQ)   // 8192

// ---------------------------------------------------------------------------
// Scratch (static __device__ arrays — allocation-free per harness rules)
// ---------------------------------------------------------------------------
__device__ unsigned short g_qh[BB*NH*SEQ*DEPTH], g_ql[BB*NH*SEQ*DEPTH];
__device__ unsigned short g_kh[BB*NH*SEQ*DEPTH], g_kl[BB*NH*SEQ*DEPTH];
__device__ unsigned short g_vh[BB*NH*SEQ*DEPTH], g_vl[BB*NH*SEQ*DEPTH];
__device__ unsigned short g_ah[MROWS*DMODEL],    g_al[MROWS*DMODEL];
__device__ unsigned short g_xh[MROWS*DMODEL],    g_xl[MROWS*DMODEL];
__device__ unsigned short g_yh[MROWS*DMODEL],    g_yl[MROWS*DMODEL];
__device__ unsigned short g_wqh[DMODEL*DMODEL],  g_wql[DMODEL*DMODEL];
__device__ unsigned short g_wkh[DMODEL*DMODEL],  g_wkl[DMODEL*DMODEL];
__device__ unsigned short g_wvh[DMODEL*DMODEL],  g_wvl[DMODEL*DMODEL];
__device__ unsigned short g_woh[DMODEL*DMODEL],  g_wol[DMODEL*DMODEL];

// ---------------------------------------------------------------------------
// Baseline-PTX helpers (no tcgen05 — harness compiles for compute_103!)
// ---------------------------------------------------------------------------
__device__ __forceinline__ uint32_t smem_u32(const void* p) {
    uint32_t r;
    asm("{ .reg .u64 t; cvta.to.shared.u64 t, %1; cvt.u32.u64 %0, t; }"
        : "=r"(r) : "l"(p));
    return r;
}
__device__ __forceinline__ void cp_async16(uint32_t saddr, const void* gaddr) {
    asm volatile("cp.async.cg.shared.global [%0], [%1], 16;"
                 :: "r"(saddr), "l"(gaddr) : "memory");
}
__device__ __forceinline__ void cp_commit() {
    asm volatile("cp.async.commit_group;" ::: "memory");
}
template <int N>
__device__ __forceinline__ void cp_wait() {
    asm volatile("cp.async.wait_group %0;" :: "n"(N) : "memory");
}
__device__ __forceinline__ void ldmx4(uint32_t* r, uint32_t a) {
    asm volatile("ldmatrix.sync.aligned.m8n8.x4.shared.b16 {%0,%1,%2,%3}, [%4];"
                 : "=r"(r[0]), "=r"(r[1]), "=r"(r[2]), "=r"(r[3]) : "r"(a));
}
__device__ __forceinline__ void ldmx4t(uint32_t* r, uint32_t a) {
    asm volatile("ldmatrix.sync.aligned.m8n8.x4.trans.shared.b16 {%0,%1,%2,%3}, [%4];"
                 : "=r"(r[0]), "=r"(r[1]), "=r"(r[2]), "=r"(r[3]) : "r"(a));
}
__device__ __forceinline__ void mma16816(float* d, const uint32_t* a, const uint32_t* b) {
    asm volatile(
        "mma.sync.aligned.m16n8k16.row.col.f32.bf16.bf16.f32 "
        "{%0,%1,%2,%3}, {%4,%5,%6,%7}, {%8,%9}, {%0,%1,%2,%3};"
        : "+f"(d[0]), "+f"(d[1]), "+f"(d[2]), "+f"(d[3])
        : "r"(a[0]), "r"(a[1]), "r"(a[2]), "r"(a[3]), "r"(b[0]), "r"(b[1]));
}

// Split a float pair into bf16 hi/lo packed b32s (low half = first value)
__device__ __forceinline__ void pack_hilo(float f0, float f1, uint32_t& h, uint32_t& l) {
    __nv_bfloat162 hb = __floats2bfloat162_rn(f0, f1);
    uint32_t hu = *reinterpret_cast<uint32_t*>(&hb);
    float r0 = f0 - __int_as_float(hu << 16);
    float r1 = f1 - __int_as_float(hu & 0xFFFF0000u);
    __nv_bfloat162 lb = __floats2bfloat162_rn(r0, r1);
    h = hu;
    l = *reinterpret_cast<uint32_t*>(&lb);
}

// FMA-pipe 2^t (t <= 0 in all our uses). deg-5 Taylor on [-0.5,0.5], err ~2.4e-6.
__device__ __forceinline__ float exp2p(float t) {
    t = fmaxf(t, -126.f);
    float z = t + 12582912.f;
    float n = z - 12582912.f;
    float f = t - n;
    float p = 0.0013333558f;
    p = fmaf(p, f, 0.0096181291f);
    p = fmaf(p, f, 0.0555041087f);
    p = fmaf(p, f, 0.2402265070f);
    p = fmaf(p, f, 0.6931471806f);
    p = fmaf(p, f, 1.0f);
    int e = (__float_as_int(z) + (127 - 0x4B400000)) << 23;
    return __int_as_float(e) * p;
}

#define L2E 1.4426950408889634f

// ---------------------------------------------------------------------------
// Batched fp32 -> bf16 hi/lo conversions
// ---------------------------------------------------------------------------
__device__ __forceinline__ void cvt_one(const float4* src, __nv_bfloat162* hi,
                                        __nv_bfloat162* lo, int i) {
    float4 v = src[i];
    uint32_t h0, l0, h1, l1;
    pack_hilo(v.x, v.y, h0, l0);
    pack_hilo(v.z, v.w, h1, l1);
    hi[2*i + 0] = *reinterpret_cast<__nv_bfloat162*>(&h0);
    hi[2*i + 1] = *reinterpret_cast<__nv_bfloat162*>(&h1);
    lo[2*i + 0] = *reinterpret_cast<__nv_bfloat162*>(&l0);
    lo[2*i + 1] = *reinterpret_cast<__nv_bfloat162*>(&l1);
}

__global__ __launch_bounds__(256) void cvt_hilo2(
    const float4* __restrict__ s0, __nv_bfloat162* __restrict__ h0, __nv_bfloat162* __restrict__ l0,
    const float4* __restrict__ s1, __nv_bfloat162* __restrict__ h1, __nv_bfloat162* __restrict__ l1,
    int n4)
{
    int i = blockIdx.x * blockDim.x + threadIdx.x;
    if (i >= n4) return;
    if (blockIdx.y == 0) cvt_one(s0, h0, l0, i);
    else                 cvt_one(s1, h1, l1, i);
}

__global__ __launch_bounds__(256) void cvt_hilo4(
    const float4* __restrict__ s0, __nv_bfloat162* __restrict__ h0, __nv_bfloat162* __restrict__ l0,
    const float4* __restrict__ s1, __nv_bfloat162* __restrict__ h1, __nv_bfloat162* __restrict__ l1,
    const float4* __restrict__ s2, __nv_bfloat162* __restrict__ h2, __nv_bfloat162* __restrict__ l2,
    const float4* __restrict__ s3, __nv_bfloat162* __restrict__ h3, __nv_bfloat162* __restrict__ l3,
    int n4)
{
    int i = blockIdx.x * blockDim.x + threadIdx.x;
    if (i >= n4) return;
    switch (blockIdx.y) {
        case 0: cvt_one(s0, h0, l0, i); break;
        case 1: cvt_one(s1, h1, l1, i); break;
        case 2: cvt_one(s2, h2, l2, i); break;
        default: cvt_one(s3, h3, l3, i); break;
    }
}

// ---------------------------------------------------------------------------
// mma.sync bf16x3 GEMM core (B loads via ldmatrix.x4 nf-pairs)
// ---------------------------------------------------------------------------
#define GK       1024
#define BKE      32
#define NSTG     (GK / BKE)          // 32
#define TPAD     40
#define TILE_B   (128 * TPAD * 2)    // 10240
#define STAGE_B  (4 * TILE_B)
#define GSMEM    (2 * STAGE_B)       // 81920

__device__ __forceinline__ void issue_stage(uint32_t sbase, int s, int k0, int m0, int n0,
                                            int tid,
                                            const unsigned short* Ah, const unsigned short* Al,
                                            const unsigned short* Bh, const unsigned short* Bl)
{
    const unsigned short* gsrc[4] = {Ah, Al, Bh, Bl};
    #pragma unroll
    for (int t = 0; t < 4; t++) {
        const int r0 = (t < 2) ? m0 : n0;
        const char* g = (const char*)(gsrc[t] + (size_t)r0 * GK + k0);
        uint32_t sb = sbase + s * STAGE_B + t * TILE_B;
        #pragma unroll
        for (int i = 0; i < 2; i++) {
            int slot = tid + i * 256;
            int row  = slot >> 2;
            int c16  = (slot & 3) * 16;
            cp_async16(sb + row * (TPAD * 2) + c16,
                       g + (size_t)row * (GK * 2) + c16);
        }
    }
}

template <int LAYOUT>
__device__ __forceinline__ void gemm_core(
    const unsigned short* Ah, const unsigned short* Al,
    const unsigned short* Bh, const unsigned short* Bl,
    float* C, unsigned short* Ch, unsigned short* Cl, float scale,
    char* smem)
{
    const int tid = threadIdx.x;
    const int wid = tid >> 5;
    const int lane = tid & 31;
    const int warp_m = wid >> 2;
    const int warp_n = wid & 3;
    const int m0 = blockIdx.y * 128;
    const int n0 = blockIdx.x * 128;

    const uint32_t sbase = smem_u32(smem);

    float d[4][4][4];
    #pragma unroll
    for (int mf = 0; mf < 4; mf++)
        #pragma unroll
        for (int nf = 0; nf < 4; nf++)
            #pragma unroll
            for (int r = 0; r < 4; r++) d[mf][nf][r] = 0.f;

    const int arow = warp_m * 64 + (lane & 15);
    const int acol8 = (lane >> 4) * 8;
    // B x4 pairing: matrices {nf,k0},{nf,k1},{nf+1,k0},{nf+1,k1}
    const int brow4 = warp_n * 32 + ((lane >> 4) & 1) * 8 + (lane & 7);
    const int bk8   = ((lane >> 3) & 1) * 8;

    issue_stage(sbase, 0, 0, m0, n0, tid, Ah, Al, Bh, Bl);
    cp_commit();

    for (int it = 0; it < NSTG; it++) {
        const int s = it & 1;
        if (it + 1 < NSTG) {
            issue_stage(sbase, s ^ 1, (it + 1) * BKE, m0, n0, tid, Ah, Al, Bh, Bl);
            cp_commit();
            cp_wait<1>();
        } else {
            cp_wait<0>();
        }
        __syncthreads();

        const uint32_t As_h = sbase + s * STAGE_B;
        const uint32_t As_l = As_h + TILE_B;
        const uint32_t Bs_h = As_h + 2 * TILE_B;
        const uint32_t Bs_l = As_h + 3 * TILE_B;

        #pragma unroll
        for (int ks = 0; ks < 2; ks++) {
            const int kb = ks * 16;
            uint32_t ah[4][4], al[4][4];
            #pragma unroll
            for (int mf = 0; mf < 4; mf++) {
                uint32_t off = (uint32_t)((arow + mf * 16) * TPAD + kb + acol8) * 2;
                ldmx4(ah[mf], As_h + off);
                ldmx4(al[mf], As_l + off);
            }
            #pragma unroll
            for (int nfp = 0; nfp < 2; nfp++) {
                uint32_t off = (uint32_t)((brow4 + nfp * 16) * TPAD + kb + bk8) * 2;
                uint32_t bh4[4], bl4[4];
                ldmx4(bh4, Bs_h + off);
                ldmx4(bl4, Bs_l + off);
                #pragma unroll
                for (int mf = 0; mf < 4; mf++) {
                    mma16816(d[mf][2*nfp],   ah[mf], bh4);
                    mma16816(d[mf][2*nfp],   ah[mf], bl4);
                    mma16816(d[mf][2*nfp],   al[mf], bh4);
                    mma16816(d[mf][2*nfp+1], ah[mf], bh4 + 2);
                    mma16816(d[mf][2*nfp+1], ah[mf], bl4 + 2);
                    mma16816(d[mf][2*nfp+1], al[mf], bh4 + 2);
                }
            }
        }
        __syncthreads();
    }

    const int g = lane >> 2;
    const int tg = lane & 3;
    #pragma unroll
    for (int mf = 0; mf < 4; mf++) {
        #pragma unroll
        for (int nf = 0; nf < 4; nf++) {
            int m = m0 + warp_m * 64 + mf * 16 + g;
            int n = n0 + warp_n * 32 + nf * 8 + tg * 2;
            #pragma unroll
            for (int half = 0; half < 2; half++) {
                float vx = d[mf][nf][half * 2 + 0] * scale;
                float vy = d[mf][nf][half * 2 + 1] * scale;
                int mm = m + half * 8;
                if (LAYOUT == 0) {
                    float2 v; v.x = vx; v.y = vy;
                    *(float2*)&C[(size_t)mm * DMODEL + n] = v;
                } else {
                    uint32_t hp, lp;
                    pack_hilo(vx, vy, hp, lp);
                    int bI = mm >> 11;
                    int sI = mm & (SEQ - 1);
                    int hI = n >> 6;
                    int dd = n & (DEPTH - 1);
                    size_t idx = (((size_t)(bI * NH + hI)) * SEQ + sI) * DEPTH + dd;
                    *(uint32_t*)&Ch[idx] = hp;
                    *(uint32_t*)&Cl[idx] = lp;
                }
            }
        }
    }
}

// Merged Q/K/V projection GEMMs: grid.z selects which.
__global__ __launch_bounds__(256) void gemm_qkv()
{
    extern __shared__ __align__(128) char smem[];
    const int z = blockIdx.z;
    if (z == 0)
        gemm_core<1>(g_xh, g_xl, g_wqh, g_wql, nullptr, g_qh, g_ql, 0.125f, smem);
    else if (z == 1)
        gemm_core<1>(g_yh, g_yl, g_wkh, g_wkl, nullptr, g_kh, g_kl, 1.0f, smem);
    else
        gemm_core<1>(g_yh, g_yl, g_wvh, g_wvl, nullptr, g_vh, g_vl, 1.0f, smem);
}

__global__ __launch_bounds__(256) void gemm_out(float* __restrict__ out)
{
    extern __shared__ __align__(128) char smem[];
    gemm_core<0>(g_ah, g_al, g_woh, g_wol, out, nullptr, nullptr, 1.0f, smem);
}

// ---------------------------------------------------------------------------
// Flash attention v4: 2 CTAs/SM (softmax of one CTA overlaps MMA of the other),
// Q fragments reloaded from smem (hoisting proven neutral — tensor-bound),
// K loads via ldmatrix.x4 ks-pairs.
// ---------------------------------------------------------------------------
#define FPITCH 72
#define FROWB  (FPITCH*2)              // 144
#define FQH    0
#define FQL    (128*FROWB)             // 18432
#define FKV0   (2*128*FROWB)           // 36864
#define FSTG   (4*64*FROWB)            // 36864
#define FKH    0
#define FKL    (64*FROWB)
#define FVH    (2*64*FROWB)
#define FVL    (3*64*FROWB)
#define FSMEM  (FKV0 + 2*FSTG)         // 110592 (x2 CTAs = 216KB <= 227KB)

__device__ __forceinline__ void flash_issue_kv(uint32_t sb, int kv0, int tid,
                                               const unsigned short* kh, const unsigned short* kl,
                                               const unsigned short* vh, const unsigned short* vl)
{
    const unsigned short* srcs[4] = {kh, kl, vh, vl};
    #pragma unroll
    for (int i = 0; i < 8; i++) {
        const int t = i >> 1;
        int slot = (i & 1) * 256 + tid;
        int r = slot >> 3;
        int c = slot & 7;
        cp_async16(sb + t * 9216 + r * 144 + c * 16,
                   (const char*)(srcs[t] + (size_t)(kv0 + r) * DEPTH) + c * 16);
    }
}

__global__ __launch_bounds__(256, 2) void flash_v4(const float* __restrict__ bias)
{
    extern __shared__ __align__(128) char smem[];
    const uint32_t sbase = smem_u32(smem);

    const int bh = blockIdx.x;
    const int q0 = blockIdx.y * 128;
    const int b  = bh >> 4;
    const int h  = bh & 15;

    const size_t hb = (size_t)bh * SEQ * DEPTH;
    const unsigned short* qhp = g_qh + hb;
    const unsigned short* qlp = g_ql + hb;
    const unsigned short* khp = g_kh + hb;
    const unsigned short* klp = g_kl + hb;
    const unsigned short* vhp = g_vh + hb;
    const unsigned short* vlp = g_vl + hb;

    const int tid = threadIdx.x;
    const int W = tid >> 5;
    const int lane = tid & 31;
    const int g = lane >> 2;
    const int tg = lane & 3;

    // ---- preload Q (hi+lo) ----
    {
        const unsigned short* src = (tid & 128) ? qlp : qhp;
        uint32_t dst = sbase + ((tid & 128) ? FQL : FQH);
        int row = tid & 127;
        #pragma unroll
        for (int c = 0; c < 8; c++)
            cp_async16(dst + row * 144 + c * 16,
                       (const char*)(src + (size_t)(q0 + row) * DEPTH) + c * 16);
    }
    cp_commit();                                   // group: Q
    flash_issue_kv(sbase + FKV0, 0, tid, khp, klp, vhp, vlp);
    cp_commit();                                   // group: KV0

    const uint32_t aoff = (uint32_t)((W * 16 + (lane & 15)) * FPITCH + ((lane >> 4) & 1) * 8) * 2;
    // K x4 ks-pairing: matrices {ks,k0},{ks,k1},{ks+1,k0},{ks+1,k1}
    const uint32_t kboff = (uint32_t)((lane & 7) * FPITCH + ((lane >> 3) & 1) * 8 +
                                      ((lane >> 4) & 1) * 16) * 2;

    float o[8][4];
    #pragma unroll
    for (int nf = 0; nf < 8; nf++)
        #pragma unroll
        for (int r = 0; r < 4; r++) o[nf][r] = 0.f;
    float mrow[2] = {-INFINITY, -INFINITY};
    float lrow[2] = {0.f, 0.f};

    const float* brow0 = bias + (size_t)(q0 + W * 16 + g) * SEQ + tg * 2;

    for (int it = 0; it < SEQ / 64; it++) {
        const int s = it & 1;
        const int k0 = it * 64;
        if (it + 1 < SEQ / 64) {
            flash_issue_kv(sbase + FKV0 + (s ^ 1) * FSTG, (it + 1) * 64, tid,
                           khp, klp, vhp, vlp);
            cp_commit();
            cp_wait<1>();
        } else {
            cp_wait<0>();
        }
        __syncthreads();

        const uint32_t SB = sbase + FKV0 + s * FSTG;

        // ---- S starts as bias ----
        float sacc[8][4];
        {
            const float* bp = brow0 + k0;
            #pragma unroll
            for (int nf = 0; nf < 8; nf++) {
                float2 b0 = *(const float2*)(bp + nf * 8);
                float2 b1 = *(const float2*)(bp + 8 * SEQ + nf * 8);
                sacc[nf][0] = b0.x; sacc[nf][1] = b0.y;
                sacc[nf][2] = b1.x; sacc[nf][3] = b1.y;
            }
        }

        // ---- S += Q K^T (bf16x3), Q frags loaded per iter, K via x4 pairs ----
        {
            uint32_t ah[4][4], al[4][4];
            #pragma unroll
            for (int ks = 0; ks < 4; ks++) {
                ldmx4(ah[ks], sbase + FQH + aoff + ks * 32);
                ldmx4(al[ks], sbase + FQL + aoff + ks * 32);
            }
            #pragma unroll
            for (int nf = 0; nf < 8; nf++) {
                const uint32_t bo = SB + (uint32_t)(nf * 8 * FPITCH * 2) + kboff;
                #pragma unroll
                for (int kp = 0; kp < 2; kp++) {
                    uint32_t kh4[4], kl4[4];
                    ldmx4(kh4, bo + FKH + kp * 64);
                    ldmx4(kl4, bo + FKL + kp * 64);
                    mma16816(sacc[nf], ah[2*kp],   kh4);
                    mma16816(sacc[nf], ah[2*kp],   kl4);
                    mma16816(sacc[nf], al[2*kp],   kh4);
                    mma16816(sacc[nf], ah[2*kp+1], kh4 + 2);
                    mma16816(sacc[nf], ah[2*kp+1], kl4 + 2);
                    mma16816(sacc[nf], al[2*kp+1], kh4 + 2);
                }
            }
        }

        // ---- online softmax (rows g and g+8; reduce over 4 tg lanes) ----
        #pragma unroll
        for (int r = 0; r < 2; r++) {
            float mx = fmaxf(sacc[0][2*r], sacc[0][2*r+1]);
            #pragma unroll
            for (int nf = 1; nf < 8; nf++)
                mx = fmaxf(mx, fmaxf(sacc[nf][2*r], sacc[nf][2*r+1]));
            mx = fmaxf(mx, __shfl_xor_sync(0xffffffffu, mx, 1));
            mx = fmaxf(mx, __shfl_xor_sync(0xffffffffu, mx, 2));
            float mnew = fmaxf(mrow[r], mx);
            float mL = mnew * L2E;
            float corr = exp2p(fmaf(mrow[r], L2E, -mL));
            float sum = 0.f;
            #pragma unroll
            for (int nf = 0; nf < 8; nf++) {
                float p0 = exp2p(fmaf(sacc[nf][2*r],   L2E, -mL));
                float p1 = exp2p(fmaf(sacc[nf][2*r+1], L2E, -mL));
                sacc[nf][2*r] = p0; sacc[nf][2*r+1] = p1;
                sum += p0 + p1;
            }
            sum += __shfl_xor_sync(0xffffffffu, sum, 1);
            sum += __shfl_xor_sync(0xffffffffu, sum, 2);
            lrow[r] = lrow[r] * corr + sum;
            mrow[r] = mnew;
            #pragma unroll
            for (int nf = 0; nf < 8; nf++) {
                o[nf][2*r]   *= corr;
                o[nf][2*r+1] *= corr;
            }
        }

        // ---- O += P V (P re-packed in-register to A-fragments, bf16x3) ----
        #pragma unroll
        for (int ks = 0; ks < 4; ks++) {
            uint32_t ph[4], pl[4];
            pack_hilo(sacc[2*ks][0],   sacc[2*ks][1],   ph[0], pl[0]);
            pack_hilo(sacc[2*ks][2],   sacc[2*ks][3],   ph[1], pl[1]);
            pack_hilo(sacc[2*ks+1][0], sacc[2*ks+1][1], ph[2], pl[2]);
            pack_hilo(sacc[2*ks+1][2], sacc[2*ks+1][3], ph[3], pl[3]);
            const uint32_t vro = (uint32_t)((ks * 16 + (lane & 15)) * FPITCH) * 2;
            #pragma unroll
            for (int nfp = 0; nfp < 4; nfp++) {
                uint32_t voff = vro + (uint32_t)((nfp * 2 + ((lane >> 4) & 1)) * 8) * 2;
                uint32_t vh4[4], vl4[4];
                ldmx4t(vh4, SB + FVH + voff);
                ldmx4t(vl4, SB + FVL + voff);
                mma16816(o[nfp*2],     ph, vh4);
                mma16816(o[nfp*2],     ph, vl4);
                mma16816(o[nfp*2],     pl, vh4);
                mma16816(o[nfp*2 + 1], ph, vh4 + 2);
                mma16816(o[nfp*2 + 1], ph, vl4 + 2);
                mma16816(o[nfp*2 + 1], pl, vh4 + 2);
            }
        }
        __syncthreads();
    }

    // ---- epilogue: normalize, emit bf16 hi/lo attn in [B,S,D] layout ----
    const float inv0 = 1.0f / lrow[0];
    const float inv1 = 1.0f / lrow[1];
    const int mr = q0 + W * 16 + g;
    #pragma unroll
    for (int nf = 0; nf < 8; nf++) {
        int col = h * DEPTH + nf * 8 + tg * 2;
        uint32_t hp, lp;
        pack_hilo(o[nf][0] * inv0, o[nf][1] * inv0, hp, lp);
        size_t i0 = ((size_t)b * SEQ + mr) * DMODEL + col;
        *(uint32_t*)&g_ah[i0] = hp;
        *(uint32_t*)&g_al[i0] = lp;
        pack_hilo(o[nf][2] * inv1, o[nf][3] * inv1, hp, lp);
        size_t i1 = ((size_t)b * SEQ + mr + 8) * DMODEL + col;
        *(uint32_t*)&g_ah[i1] = hp;
        *(uint32_t*)&g_al[i1] = lp;
    }
}

// ---------------------------------------------------------------------------
// Launch
// ---------------------------------------------------------------------------
extern "C" void kernel_launch(void* const* d_in, const int* in_sizes, int n_in,
                              void* d_out, int out_size)
{
    const float* x    = (const float*)d_in[0];
    const float* y    = (const float*)d_in[1];
    const float* bias = (const float*)d_in[2];
    const float* Wq   = (const float*)d_in[3];
    const float* Wk   = (const float*)d_in[4];
    const float* Wv   = (const float*)d_in[5];
    const float* Wo   = (const float*)d_in[6];
    float* out = (float*)d_out;

    unsigned short *xh, *xl, *yh, *yl;
    unsigned short *wqh, *wql, *wkh, *wkl, *wvh, *wvl, *woh, *wol;
    cudaGetSymbolAddress((void**)&xh, g_xh);   cudaGetSymbolAddress((void**)&xl, g_xl);
    cudaGetSymbolAddress((void**)&yh, g_yh);   cudaGetSymbolAddress((void**)&yl, g_yl);
    cudaGetSymbolAddress((void**)&wqh, g_wqh); cudaGetSymbolAddress((void**)&wql, g_wql);
    cudaGetSymbolAddress((void**)&wkh, g_wkh); cudaGetSymbolAddress((void**)&wkl, g_wkl);
    cudaGetSymbolAddress((void**)&wvh, g_wvh); cudaGetSymbolAddress((void**)&wvl, g_wvl);
    cudaGetSymbolAddress((void**)&woh, g_woh); cudaGetSymbolAddress((void**)&wol, g_wol);

    cudaFuncSetAttribute(gemm_qkv, cudaFuncAttributeMaxDynamicSharedMemorySize, GSMEM);
    cudaFuncSetAttribute(gemm_out, cudaFuncAttributeMaxDynamicSharedMemorySize, GSMEM);
    cudaFuncSetAttribute(flash_v4, cudaFuncAttributeMaxDynamicSharedMemorySize, FSMEM);

    const int n4big = MROWS * DMODEL / 4;
    const int n4w   = DMODEL * DMODEL / 4;

    cvt_hilo2<<<dim3(n4big/256, 2), 256>>>(
        (const float4*)x, (__nv_bfloat162*)xh, (__nv_bfloat162*)xl,
        (const float4*)y, (__nv_bfloat162*)yh, (__nv_bfloat162*)yl, n4big);
    cvt_hilo4<<<dim3(n4w/256, 4), 256>>>(
        (const float4*)Wq, (__nv_bfloat162*)wqh, (__nv_bfloat162*)wql,
        (const float4*)Wk, (__nv_bfloat162*)wkh, (__nv_bfloat162*)wkl,
        (const float4*)Wv, (__nv_bfloat162*)wvh, (__nv_bfloat162*)wvl,
        (const float4*)Wo, (__nv_bfloat162*)woh, (__nv_bfloat162*)wol, n4w);

    // merged Q/K/V projections: one launch, 1536 tiles
    gemm_qkv<<<dim3(DMODEL / 128, MROWS / 128, 3), 256, GSMEM>>>();

    dim3 fgrid(BB * NH, SEQ / 128);           // (64, 16)
    flash_v4<<<fgrid, dim3(256), FSMEM>>>(bias);

    gemm_out<<<dim3(DMODEL / 128, MROWS / 128), 256, GSMEM>>>(out);
}